// round 2
// baseline (speedup 1.0000x reference)
#include <cuda_runtime.h>
#include <cuda_bf16.h>
#include <cstdint>

#define N_NODES 100000
#define N_EDGES 1600000
#define IN_F 512
#define HID_F 128
#define N_CLS 64

// ---------------- scratch (device globals; referenced ONLY inside kernels) --
__device__ float g_xw1[(size_t)N_NODES * HID_F];   // x@w1+b1
__device__ float g_h[(size_t)N_NODES * HID_F];     // relu(A @ xw1)
__device__ float g_hw2[(size_t)N_NODES * N_CLS];   // h@w2+b2
__device__ int   g_deg[N_NODES];
__device__ int   g_rowptr[N_NODES + 1];
__device__ int   g_cursor[N_NODES];
__device__ int   g_scol[N_EDGES];
__device__ float g_sval[N_EDGES];

// ---------------- CSR build --------------------------------------------------
__global__ void zero_deg_kernel() {
    int i = blockIdx.x * blockDim.x + threadIdx.x;
    if (i < N_NODES) g_deg[i] = 0;
}

__global__ void hist_kernel(const int* __restrict__ row) {
    int e = blockIdx.x * blockDim.x + threadIdx.x;
    if (e < N_EDGES) atomicAdd(&g_deg[row[e]], 1);
}

// single-block exclusive scan over N_NODES degrees -> rowptr, cursor
__global__ void scan_kernel() {
    const int T = 1024;
    __shared__ int sh[T];
    int tid = threadIdx.x;
    const int chunk = (N_NODES + T - 1) / T;  // 98
    int start = tid * chunk;
    int end = min(start + chunk, N_NODES);
    int s = 0;
    for (int i = start; i < end; i++) s += g_deg[i];
    sh[tid] = s;
    __syncthreads();
    for (int off = 1; off < T; off <<= 1) {
        int v = (tid >= off) ? sh[tid - off] : 0;
        __syncthreads();
        sh[tid] += v;
        __syncthreads();
    }
    int run = sh[tid] - s;  // exclusive prefix
    for (int i = start; i < end; i++) {
        int d = g_deg[i];
        g_rowptr[i] = run;
        g_cursor[i] = run;
        run += d;
    }
    if (tid == T - 1) g_rowptr[N_NODES] = sh[T - 1];
}

__global__ void scatter_kernel(const int* __restrict__ row,
                               const int* __restrict__ col,
                               const float* __restrict__ val) {
    int e = blockIdx.x * blockDim.x + threadIdx.x;
    if (e >= N_EDGES) return;
    int r = row[e];
    int p = atomicAdd(&g_cursor[r], 1);
    g_scol[p] = col[e];
    g_sval[p] = val[e];
}

// ---------------- GEMM1: [N,512] @ [512,128] + b1 -> g_xw1 ------------------
// BM=128, BN=128, BK=16, 256 threads, 8x8 per thread
__global__ __launch_bounds__(256) void gemm1_kernel(const float* __restrict__ A,
                                                    const float* __restrict__ B,
                                                    const float* __restrict__ bias) {
    const int K = IN_F, Nn = HID_F;
    __shared__ float As[16][128];
    __shared__ float Bs[16][128];
    int tid = threadIdx.x;
    int block_row = blockIdx.x * 128;
    int tx = tid & 15;
    int ty = tid >> 4;
    float acc[8][8];
#pragma unroll
    for (int i = 0; i < 8; i++)
#pragma unroll
        for (int j = 0; j < 8; j++) acc[i][j] = 0.f;

    for (int k0 = 0; k0 < K; k0 += 16) {
#pragma unroll
        for (int i = 0; i < 2; i++) {
            int s = tid + i * 256;
            int ar = s >> 2, ak = (s & 3) << 2;
            float4 av = make_float4(0.f, 0.f, 0.f, 0.f);
            int grow = block_row + ar;
            if (grow < N_NODES)
                av = *(const float4*)(A + (size_t)grow * K + k0 + ak);
            As[ak + 0][ar] = av.x;
            As[ak + 1][ar] = av.y;
            As[ak + 2][ar] = av.z;
            As[ak + 3][ar] = av.w;
            int bk = s >> 5, bn = (s & 31) << 2;
            float4 bv = *(const float4*)(B + (size_t)(k0 + bk) * Nn + bn);
            *(float4*)&Bs[bk][bn] = bv;
        }
        __syncthreads();
#pragma unroll
        for (int kk = 0; kk < 16; kk++) {
            float ra[8], rb[8];
#pragma unroll
            for (int i = 0; i < 8; i++) ra[i] = As[kk][ty * 8 + i];
#pragma unroll
            for (int j = 0; j < 8; j++) rb[j] = Bs[kk][tx * 8 + j];
#pragma unroll
            for (int i = 0; i < 8; i++)
#pragma unroll
                for (int j = 0; j < 8; j++) acc[i][j] += ra[i] * rb[j];
        }
        __syncthreads();
    }
#pragma unroll
    for (int i = 0; i < 8; i++) {
        int grow = block_row + ty * 8 + i;
        if (grow >= N_NODES) continue;
#pragma unroll
        for (int j = 0; j < 8; j += 4) {
            int gc = tx * 8 + j;
            float4 o;
            o.x = acc[i][j + 0] + bias[gc + 0];
            o.y = acc[i][j + 1] + bias[gc + 1];
            o.z = acc[i][j + 2] + bias[gc + 2];
            o.w = acc[i][j + 3] + bias[gc + 3];
            *(float4*)(g_xw1 + (size_t)grow * Nn + gc) = o;
        }
    }
}

// ---------------- SpMM (CSR, warp per row), F=128, fused relu ---------------
// reads g_xw1, writes g_h (globals referenced directly — device addresses)
__global__ void spmm128_relu_kernel() {
    int warp = (blockIdx.x * blockDim.x + threadIdx.x) >> 5;
    if (warp >= N_NODES) return;
    int lane = threadIdx.x & 31;
    int beg = g_rowptr[warp], end = g_rowptr[warp + 1];
    float4 acc = make_float4(0.f, 0.f, 0.f, 0.f);
    for (int e = beg; e < end; e++) {
        int c = g_scol[e];
        float v = g_sval[e];
        float4 xv = ((const float4*)(g_xw1 + (size_t)c * HID_F))[lane];
        acc.x += v * xv.x;
        acc.y += v * xv.y;
        acc.z += v * xv.z;
        acc.w += v * xv.w;
    }
    acc.x = fmaxf(acc.x, 0.f);
    acc.y = fmaxf(acc.y, 0.f);
    acc.z = fmaxf(acc.z, 0.f);
    acc.w = fmaxf(acc.w, 0.f);
    ((float4*)(g_h + (size_t)warp * HID_F))[lane] = acc;
}

// ---------------- GEMM2: g_h [N,128] @ w2 [128,64] + b2 -> g_hw2 ------------
__global__ __launch_bounds__(256) void gemm2_kernel(const float* __restrict__ W2,
                                                    const float* __restrict__ b2) {
    __shared__ float sw[HID_F * N_CLS];   // 32 KB
    __shared__ float shh[4][HID_F];
    int tid = threadIdx.x;
    for (int i = tid; i < HID_F * N_CLS; i += 256) sw[i] = W2[i];
    float bias = b2[tid & 63];
    int rl = tid >> 6;  // 0..3
    int j = tid & 63;
    __syncthreads();
    for (int row0 = blockIdx.x * 4; row0 < N_NODES; row0 += gridDim.x * 4) {
        for (int i = tid; i < 4 * HID_F; i += 256) {
            int r = row0 + (i >> 7);
            shh[i >> 7][i & 127] = (r < N_NODES) ? g_h[(size_t)r * HID_F + (i & 127)] : 0.f;
        }
        __syncthreads();
        float acc = 0.f;
#pragma unroll 8
        for (int k = 0; k < HID_F; k++) acc += shh[rl][k] * sw[k * N_CLS + j];
        int r = row0 + rl;
        if (r < N_NODES) g_hw2[(size_t)r * N_CLS + j] = acc + bias;
        __syncthreads();
    }
}

// ---------------- SpMM F=64 (final output; reads g_hw2) ---------------------
__global__ void spmm64_kernel(float* __restrict__ dst) {
    int warp = (blockIdx.x * blockDim.x + threadIdx.x) >> 5;
    if (warp >= N_NODES) return;
    int lane = threadIdx.x & 31;
    int beg = g_rowptr[warp], end = g_rowptr[warp + 1];
    float2 acc = make_float2(0.f, 0.f);
    for (int e = beg; e < end; e++) {
        int c = g_scol[e];
        float v = g_sval[e];
        float2 xv = ((const float2*)(g_hw2 + (size_t)c * N_CLS))[lane];
        acc.x += v * xv.x;
        acc.y += v * xv.y;
    }
    ((float2*)(dst + (size_t)warp * N_CLS))[lane] = acc;
}

// ---------------- launch -----------------------------------------------------
extern "C" void kernel_launch(void* const* d_in, const int* in_sizes, int n_in,
                              void* d_out, int out_size) {
    // Identify inputs by element count (robust to metadata ordering).
    const float* x = nullptr; const float* w1 = nullptr; const float* b1 = nullptr;
    const float* w2 = nullptr; const float* b2 = nullptr;
    const void* edge_arrs[3] = {nullptr, nullptr, nullptr};
    int n_edge_arrs = 0;
    for (int i = 0; i < n_in; i++) {
        long sz = in_sizes[i];
        if (sz == (long)N_NODES * IN_F)      x  = (const float*)d_in[i];
        else if (sz == IN_F * HID_F)         w1 = (const float*)d_in[i];
        else if (sz == HID_F * N_CLS)        w2 = (const float*)d_in[i];
        else if (sz == HID_F)                b1 = (const float*)d_in[i];
        else if (sz == N_CLS)                b2 = (const float*)d_in[i];
        else if (sz == N_EDGES && n_edge_arrs < 3) edge_arrs[n_edge_arrs++] = d_in[i];
    }
    // The three E-sized arrays keep dict order: adj_row, adj_col, adj_val
    const int*   row = (const int*)edge_arrs[0];
    const int*   col = (const int*)edge_arrs[1];
    const float* val = (const float*)edge_arrs[2];
    float* out = (float*)d_out;

    // CSR build (shared by both SpMMs)
    zero_deg_kernel<<<(N_NODES + 511) / 512, 512>>>();
    hist_kernel<<<(N_EDGES + 511) / 512, 512>>>(row);
    scan_kernel<<<1, 1024>>>();
    scatter_kernel<<<(N_EDGES + 511) / 512, 512>>>(row, col, val);

    // layer 1
    gemm1_kernel<<<(N_NODES + 127) / 128, 256>>>(x, w1, b1);
    spmm128_relu_kernel<<<(N_NODES * 32 + 255) / 256, 256>>>();

    // layer 2
    gemm2_kernel<<<2048, 256>>>(w2, b2);
    spmm64_kernel<<<(N_NODES * 32 + 255) / 256, 256>>>(out);
}

// round 3
// speedup vs baseline: 1.3711x; 1.3711x over previous
#include <cuda_runtime.h>
#include <cuda_bf16.h>
#include <cstdint>

#define N_NODES 100000
#define N_EDGES 1600000
#define IN_F 512
#define HID_F 128
#define N_CLS 64

// ---------------- scratch (device globals; referenced ONLY inside kernels) --
__device__ float g_xw1[(size_t)N_NODES * HID_F];   // x@w1+b1
__device__ float g_h[(size_t)N_NODES * HID_F];     // relu(A @ xw1)
__device__ float g_hw2[(size_t)N_NODES * N_CLS];   // h@w2+b2
__device__ int   g_deg[N_NODES];
__device__ int   g_rowptr[N_NODES + 1];
__device__ int   g_cursor[N_NODES];
__device__ int   g_scol[N_EDGES];
__device__ float g_sval[N_EDGES];

// ---------------- CSR build --------------------------------------------------
__global__ void zero_deg_kernel() {
    int i = blockIdx.x * blockDim.x + threadIdx.x;
    if (i < N_NODES) g_deg[i] = 0;
}

__global__ void hist_kernel(const int* __restrict__ row) {
    int e = blockIdx.x * blockDim.x + threadIdx.x;
    if (e < N_EDGES) atomicAdd(&g_deg[row[e]], 1);
}

// single-block exclusive scan over N_NODES degrees -> rowptr, cursor
__global__ void scan_kernel() {
    const int T = 1024;
    __shared__ int sh[T];
    int tid = threadIdx.x;
    const int chunk = (N_NODES + T - 1) / T;  // 98
    int start = tid * chunk;
    int end = min(start + chunk, N_NODES);
    int s = 0;
    for (int i = start; i < end; i++) s += g_deg[i];
    sh[tid] = s;
    __syncthreads();
    for (int off = 1; off < T; off <<= 1) {
        int v = (tid >= off) ? sh[tid - off] : 0;
        __syncthreads();
        sh[tid] += v;
        __syncthreads();
    }
    int run = sh[tid] - s;  // exclusive prefix
    for (int i = start; i < end; i++) {
        int d = g_deg[i];
        g_rowptr[i] = run;
        g_cursor[i] = run;
        run += d;
    }
    if (tid == T - 1) g_rowptr[N_NODES] = sh[T - 1];
}

__global__ void scatter_kernel(const int* __restrict__ row,
                               const int* __restrict__ col,
                               const float* __restrict__ val) {
    int e = blockIdx.x * blockDim.x + threadIdx.x;
    if (e >= N_EDGES) return;
    int r = row[e];
    int p = atomicAdd(&g_cursor[r], 1);
    g_scol[p] = col[e];
    g_sval[p] = val[e];
}

// ---------------- GEMM1 (tf32 tensor cores) ---------------------------------
// C[128 x 128] per block, K=512.  256 threads = 8 warps (2 m x 4 n).
// Each warp: 64 rows x 32 cols = 4 m-tiles x 4 n-tiles of m16n8k8.
__device__ __forceinline__ uint32_t f2tf32(float f) {
    uint32_t r;
    asm("cvt.rna.tf32.f32 %0, %1;" : "=r"(r) : "f"(f));
    return r;
}

__global__ __launch_bounds__(256) void gemm1_tf32_kernel(const float* __restrict__ A,
                                                         const float* __restrict__ B,
                                                         const float* __restrict__ bias) {
    const int K = IN_F;                 // 512
    __shared__ uint32_t As[128][20];    // [m][k] BK=16 padded to 20 (conflict-free frag loads)
    __shared__ uint32_t Bs[16][136];    // [k][n] BN=128 padded to 136 (conflict-free frag loads)
    int tid = threadIdx.x;
    int wid = tid >> 5, lane = tid & 31;
    int grp = lane >> 2, q = lane & 3;
    int warp_m = wid >> 2;              // 0..1
    int warp_n = wid & 3;               // 0..3
    int m_warp = warp_m * 64;
    int n_warp = warp_n * 32;
    int block_row = blockIdx.x * 128;

    float acc[4][4][4];
#pragma unroll
    for (int mt = 0; mt < 4; mt++)
#pragma unroll
        for (int nt = 0; nt < 4; nt++)
#pragma unroll
            for (int i = 0; i < 4; i++) acc[mt][nt][i] = 0.f;

    // A-tile load map: per pass 64 rows x 16 k; r = tid>>2, aj = (tid&3)*4
    int ar = tid >> 2;                  // 0..63
    int aj = (tid & 3) << 2;            // 0,4,8,12
    // B-tile load map: per pass 8 k-rows; k = wid, c = (tid&31)*4
    int bc = (tid & 31) << 2;

    for (int k0 = 0; k0 < K; k0 += 16) {
#pragma unroll
        for (int p = 0; p < 2; p++) {
            int r = ar + p * 64;
            int grow = block_row + r;
            float4 v = make_float4(0.f, 0.f, 0.f, 0.f);
            if (grow < N_NODES) v = *(const float4*)(A + (size_t)grow * K + k0 + aj);
            uint4 t;
            t.x = f2tf32(v.x); t.y = f2tf32(v.y); t.z = f2tf32(v.z); t.w = f2tf32(v.w);
            *(uint4*)&As[r][aj] = t;
        }
#pragma unroll
        for (int p = 0; p < 2; p++) {
            int kk = wid + p * 8;
            float4 v = *(const float4*)(B + (size_t)(k0 + kk) * HID_F + bc);
            uint4 t;
            t.x = f2tf32(v.x); t.y = f2tf32(v.y); t.z = f2tf32(v.z); t.w = f2tf32(v.w);
            *(uint4*)&Bs[kk][bc] = t;
        }
        __syncthreads();
#pragma unroll
        for (int ks = 0; ks < 2; ks++) {
            int kb = ks * 8;
            uint32_t afr[4][4], bfr[4][2];
#pragma unroll
            for (int mt = 0; mt < 4; mt++) {
                int m0 = m_warp + mt * 16;
                afr[mt][0] = As[m0 + grp][kb + q];
                afr[mt][1] = As[m0 + grp + 8][kb + q];
                afr[mt][2] = As[m0 + grp][kb + q + 4];
                afr[mt][3] = As[m0 + grp + 8][kb + q + 4];
            }
#pragma unroll
            for (int nt = 0; nt < 4; nt++) {
                int n0 = n_warp + nt * 8;
                bfr[nt][0] = Bs[kb + q][n0 + grp];
                bfr[nt][1] = Bs[kb + q + 4][n0 + grp];
            }
#pragma unroll
            for (int mt = 0; mt < 4; mt++)
#pragma unroll
                for (int nt = 0; nt < 4; nt++)
                    asm volatile(
                        "mma.sync.aligned.m16n8k8.row.col.f32.tf32.tf32.f32 "
                        "{%0,%1,%2,%3}, {%4,%5,%6,%7}, {%8,%9}, {%0,%1,%2,%3};"
                        : "+f"(acc[mt][nt][0]), "+f"(acc[mt][nt][1]),
                          "+f"(acc[mt][nt][2]), "+f"(acc[mt][nt][3])
                        : "r"(afr[mt][0]), "r"(afr[mt][1]),
                          "r"(afr[mt][2]), "r"(afr[mt][3]),
                          "r"(bfr[nt][0]), "r"(bfr[nt][1]));
        }
        __syncthreads();
    }

    // writeback with bias
#pragma unroll
    for (int mt = 0; mt < 4; mt++) {
        int r0 = block_row + m_warp + mt * 16 + grp;
        int r1 = r0 + 8;
#pragma unroll
        for (int nt = 0; nt < 4; nt++) {
            int c = n_warp + nt * 8 + q * 2;
            float bv0 = __ldg(bias + c), bv1 = __ldg(bias + c + 1);
            if (r0 < N_NODES) {
                float2 o = make_float2(acc[mt][nt][0] + bv0, acc[mt][nt][1] + bv1);
                *(float2*)(g_xw1 + (size_t)r0 * HID_F + c) = o;
            }
            if (r1 < N_NODES) {
                float2 o = make_float2(acc[mt][nt][2] + bv0, acc[mt][nt][3] + bv1);
                *(float2*)(g_xw1 + (size_t)r1 * HID_F + c) = o;
            }
        }
    }
}

// ---------------- SpMM (CSR, warp per row), F=128, fused relu ---------------
__global__ void spmm128_relu_kernel() {
    int warp = (blockIdx.x * blockDim.x + threadIdx.x) >> 5;
    if (warp >= N_NODES) return;
    int lane = threadIdx.x & 31;
    int beg = g_rowptr[warp], end = g_rowptr[warp + 1];
    float4 acc = make_float4(0.f, 0.f, 0.f, 0.f);
    for (int e = beg; e < end; e++) {
        int c = g_scol[e];
        float v = g_sval[e];
        float4 xv = ((const float4*)(g_xw1 + (size_t)c * HID_F))[lane];
        acc.x += v * xv.x;
        acc.y += v * xv.y;
        acc.z += v * xv.z;
        acc.w += v * xv.w;
    }
    acc.x = fmaxf(acc.x, 0.f);
    acc.y = fmaxf(acc.y, 0.f);
    acc.z = fmaxf(acc.z, 0.f);
    acc.w = fmaxf(acc.w, 0.f);
    ((float4*)(g_h + (size_t)warp * HID_F))[lane] = acc;
}

// ---------------- GEMM2: g_h [N,128] @ w2 [128,64] + b2 -> g_hw2 ------------
__global__ __launch_bounds__(256) void gemm2_kernel(const float* __restrict__ W2,
                                                    const float* __restrict__ b2) {
    __shared__ float sw[HID_F * N_CLS];   // 32 KB
    __shared__ float shh[4][HID_F];
    int tid = threadIdx.x;
    for (int i = tid; i < HID_F * N_CLS; i += 256) sw[i] = W2[i];
    float bias = b2[tid & 63];
    int rl = tid >> 6;  // 0..3
    int j = tid & 63;
    __syncthreads();
    for (int row0 = blockIdx.x * 4; row0 < N_NODES; row0 += gridDim.x * 4) {
        for (int i = tid; i < 4 * HID_F; i += 256) {
            int r = row0 + (i >> 7);
            shh[i >> 7][i & 127] = (r < N_NODES) ? g_h[(size_t)r * HID_F + (i & 127)] : 0.f;
        }
        __syncthreads();
        float acc = 0.f;
#pragma unroll 8
        for (int k = 0; k < HID_F; k++) acc += shh[rl][k] * sw[k * N_CLS + j];
        int r = row0 + rl;
        if (r < N_NODES) g_hw2[(size_t)r * N_CLS + j] = acc + bias;
        __syncthreads();
    }
}

// ---------------- SpMM F=64 (final output; reads g_hw2) ---------------------
__global__ void spmm64_kernel(float* __restrict__ dst) {
    int warp = (blockIdx.x * blockDim.x + threadIdx.x) >> 5;
    if (warp >= N_NODES) return;
    int lane = threadIdx.x & 31;
    int beg = g_rowptr[warp], end = g_rowptr[warp + 1];
    float2 acc = make_float2(0.f, 0.f);
    for (int e = beg; e < end; e++) {
        int c = g_scol[e];
        float v = g_sval[e];
        float2 xv = ((const float2*)(g_hw2 + (size_t)c * N_CLS))[lane];
        acc.x += v * xv.x;
        acc.y += v * xv.y;
    }
    ((float2*)(dst + (size_t)warp * N_CLS))[lane] = acc;
}

// ---------------- launch -----------------------------------------------------
extern "C" void kernel_launch(void* const* d_in, const int* in_sizes, int n_in,
                              void* d_out, int out_size) {
    // Identify inputs by element count (robust to metadata ordering).
    const float* x = nullptr; const float* w1 = nullptr; const float* b1 = nullptr;
    const float* w2 = nullptr; const float* b2 = nullptr;
    const void* edge_arrs[3] = {nullptr, nullptr, nullptr};
    int n_edge_arrs = 0;
    for (int i = 0; i < n_in; i++) {
        long sz = in_sizes[i];
        if (sz == (long)N_NODES * IN_F)      x  = (const float*)d_in[i];
        else if (sz == IN_F * HID_F)         w1 = (const float*)d_in[i];
        else if (sz == HID_F * N_CLS)        w2 = (const float*)d_in[i];
        else if (sz == HID_F)                b1 = (const float*)d_in[i];
        else if (sz == N_CLS)                b2 = (const float*)d_in[i];
        else if (sz == N_EDGES && n_edge_arrs < 3) edge_arrs[n_edge_arrs++] = d_in[i];
    }
    const int*   row = (const int*)edge_arrs[0];
    const int*   col = (const int*)edge_arrs[1];
    const float* val = (const float*)edge_arrs[2];
    float* out = (float*)d_out;

    // One-time stream/event creation (first call is the uncaptured correctness
    // run; the captured call reuses them — no allocation inside capture).
    static cudaStream_t s_side = nullptr;
    static cudaEvent_t ev_fork = nullptr, ev_join = nullptr;
    if (s_side == nullptr) {
        cudaStreamCreate(&s_side);
        cudaEventCreateWithFlags(&ev_fork, cudaEventDisableTiming);
        cudaEventCreateWithFlags(&ev_join, cudaEventDisableTiming);
    }

    // Fork: CSR build (L2/atomic-bound) overlaps gemm1 (tensor-bound).
    cudaEventRecord(ev_fork, 0);
    cudaStreamWaitEvent(s_side, ev_fork, 0);
    zero_deg_kernel<<<(N_NODES + 511) / 512, 512, 0, s_side>>>();
    hist_kernel<<<(N_EDGES + 511) / 512, 512, 0, s_side>>>(row);
    scan_kernel<<<1, 1024, 0, s_side>>>();
    scatter_kernel<<<(N_EDGES + 511) / 512, 512, 0, s_side>>>(row, col, val);
    cudaEventRecord(ev_join, s_side);

    gemm1_tf32_kernel<<<(N_NODES + 127) / 128, 256>>>(x, w1, b1);

    // Join: spmm128 needs both gemm1 output and CSR.
    cudaStreamWaitEvent(0, ev_join, 0);
    spmm128_relu_kernel<<<(N_NODES * 32 + 255) / 256, 256>>>();

    gemm2_kernel<<<2048, 256>>>(w2, b2);
    spmm64_kernel<<<(N_NODES * 32 + 255) / 256, 256>>>(out);
}